// round 6
// baseline (speedup 1.0000x reference)
#include <cuda_runtime.h>
#include <cuda_fp16.h>
#include <math.h>
#include <stdint.h>

// Problem constants
#define Bb 2
#define Hh 8
#define Ss 2048
#define Dd 512
#define Mrows (Bb * Ss)          // 4096
#define CONCAT_K (Hh * Dd)       // 4096

// ---------------------------------------------------------------------------
// Scratch (device globals; allocation is forbidden)
// ---------------------------------------------------------------------------
__device__ __half gx16[(size_t)Mrows * Dd];                 // 4 MB   [m][d]
__device__ __half gWqt16[(size_t)Hh * Dd * Dd];             // 4 MB   [h][e][d]
__device__ __half gWkt16[(size_t)Hh * Dd * Dd];
__device__ __half gWvt16[(size_t)Hh * Dd * Dd];
__device__ __half gWot16[(size_t)Dd * CONCAT_K];            // 4 MB   [e][hd]
__device__ __half gQ16[(size_t)Hh * Mrows * Dd];            // 32 MB  [h][m][e]
__device__ __half gK16[(size_t)Hh * Mrows * Dd];            // 32 MB
__device__ __half gV16[(size_t)Hh * Mrows * Dd];            // 32 MB  [h][m][e]
__device__ __half gVt16[(size_t)Hh * Dd * Mrows];           // 32 MB  [h][e][m]
__device__ float  gS[(size_t)Bb * Hh * Ss * Ss];            // 256 MB [z][q][k]
__device__ __half gP16[(size_t)Bb * Hh * Ss * Ss];          // 128 MB [z][q][k]
__device__ __half gC16[(size_t)Mrows * CONCAT_K];           // 32 MB  [m][h*D+e]

// ---------------------------------------------------------------------------
// helpers
// ---------------------------------------------------------------------------
__device__ __forceinline__ uint32_t smem_u32(const void* p) {
    uint32_t a;
    asm("{ .reg .u64 t; cvta.to.shared.u64 t, %1; cvt.u32.u64 %0, t; }" : "=r"(a) : "l"(p));
    return a;
}
#define CP16(dst, src) asm volatile("cp.async.cg.shared.global [%0], [%1], 16;" :: "r"(dst), "l"(src))
#define CP_COMMIT()    asm volatile("cp.async.commit_group;" ::: "memory")
#define CP_WAIT1()     asm volatile("cp.async.wait_group 1;" ::: "memory")

#define LDSM4(r, addr)                                                              \
    asm volatile("ldmatrix.sync.aligned.m8n8.x4.shared.b16 {%0,%1,%2,%3}, [%4];"    \
        : "=r"((r)[0]), "=r"((r)[1]), "=r"((r)[2]), "=r"((r)[3]) : "r"(addr))

__device__ __forceinline__ void mma16816(float* c, const uint32_t* a, const uint32_t* b) {
    asm volatile(
        "mma.sync.aligned.m16n8k16.row.col.f32.f16.f16.f32 "
        "{%0,%1,%2,%3},{%4,%5,%6,%7},{%8,%9},{%0,%1,%2,%3};\n"
        : "+f"(c[0]), "+f"(c[1]), "+f"(c[2]), "+f"(c[3])
        : "r"(a[0]), "r"(a[1]), "r"(a[2]), "r"(a[3]), "r"(b[0]), "r"(b[1]));
}

// ---------------------------------------------------------------------------
// fp16 GEMM: C = alpha * A @ B^T (+ bias) (+ resid)
// A: [M,K] fp16 K-major (lda halves), B: [N,K] fp16 K-major (ldb halves).
// CTA tile 256x128, K-chunk 64, 3-stage cp.async pipeline, 256 threads,
// 8 warps (4x2), warp tile 64x64, mma m16n8k16, frags via ldmatrix.x4.
// Smem rows: 64 halves data + 16B pad = 144B (LDSM 8-row phases hit all 32
// banks exactly once -> conflict-free).
//
// MODE: 0 = merged QKV proj (z = which*8+h, half out),
//       1 = QK^T (z=b*8+h, f32 out, alpha),
//       2 = P@V (z=b*8+h, half out into concat),
//       3 = out proj (f32 + bias + resid)
// ---------------------------------------------------------------------------
#define ROW_B   144u
#define A_BYTES (256u * ROW_B)          // 36864
#define B_BYTES (128u * ROW_B)          // 18432
#define STAGE_B (A_BYTES + B_BYTES)     // 55296
#define HG_SMEM (3 * 55296)             // 165888

template <int MODE>
__global__ __launch_bounds__(256)
void hgemm(const __half* __restrict__ A0, const __half* __restrict__ B0,
           const __half* __restrict__ B1v, const __half* __restrict__ B2v,
           void* __restrict__ C0, void* __restrict__ C1v, void* __restrict__ C2v,
           const float* __restrict__ bias0, const float* __restrict__ bias1,
           const float* __restrict__ bias2, const float* __restrict__ resid0,
           int K, int lda, int ldb, int ldc, float alpha)
{
    extern __shared__ char sm[];
    const uint32_t sbase = smem_u32(sm);

    const int tid = threadIdx.x;
    const int lane = tid & 31;
    const int wid = tid >> 5;
    const int g = lane >> 2;
    const int tig = lane & 3;
    const int warp_m = wid >> 1;   // 0..3  (64-row slabs of 256)
    const int warp_n = wid & 1;    // 0..1  (64-col slabs of 128)
    const int bx = blockIdx.x, by = blockIdx.y;

    const __half* A = A0;
    const __half* B = B0;
    const float* bias = bias0;
    float* Cf = (float*)C0;
    __half* Ch = (__half*)C0;
    {
        const int z = blockIdx.z;
        if (MODE == 0) {
            const int which = z >> 3, h = z & 7;
            const __half* W = (which == 0) ? B0 : ((which == 1) ? B1v : B2v);
            B = W + (size_t)h * Dd * Dd;
            __half* Co = (__half*)((which == 0) ? C0 : ((which == 1) ? C1v : C2v));
            Ch = Co + (size_t)h * Mrows * Dd;
            const float* bs = (which == 0) ? bias0 : ((which == 1) ? bias1 : bias2);
            bias = bs + (size_t)h * Dd;
        } else if (MODE == 1) {
            const int h = z & 7, b = z >> 3;
            const size_t off = ((size_t)h * Mrows + (size_t)b * Ss) * Dd;
            A += off; B += off;
            Cf += (size_t)z * Ss * Ss;
        } else if (MODE == 2) {
            const int h = z & 7, b = z >> 3;
            A += (size_t)z * Ss * Ss;
            B += (size_t)h * Dd * Mrows + (size_t)b * Ss;
            Ch += (size_t)b * Ss * CONCAT_K + (size_t)h * Dd;
        }
    }

    const __half* Arow = A + (size_t)(by * 256) * lda;
    const __half* Brow = B + (size_t)(bx * 128) * ldb;

    // per-lane LDSM addressing components
    const int lr = lane & 7;
    const uint32_t aRow = (uint32_t)(warp_m * 64 + lr + 8 * ((lane >> 3) & 1));
    const uint32_t aK   = (uint32_t)(16 * (lane >> 4));
    const uint32_t bRow = (uint32_t)(warp_n * 64 + lr + 8 * (lane >> 4));
    const uint32_t bK   = (uint32_t)(16 * ((lane >> 3) & 1));

    auto issue = [&](int c, int st) {
        const uint32_t sA = sbase + (uint32_t)st * STAGE_B;
        const uint32_t sB = sA + A_BYTES;
        const __half* Ac = Arow + (size_t)c * 64;
        const __half* Bc = Brow + (size_t)c * 64;
#pragma unroll
        for (int t = 0; t < 8; t++) {
            const int s = tid + t * 256;
            const int r = s >> 3, f = s & 7;
            CP16(sA + (uint32_t)r * ROW_B + f * 16, Ac + (size_t)r * lda + f * 8);
        }
#pragma unroll
        for (int t = 0; t < 4; t++) {
            const int s = tid + t * 256;
            const int r = s >> 3, f = s & 7;
            CP16(sB + (uint32_t)r * ROW_B + f * 16, Bc + (size_t)r * ldb + f * 8);
        }
    };

    float acc[4][8][4];
#pragma unroll
    for (int mi = 0; mi < 4; mi++)
#pragma unroll
        for (int j = 0; j < 8; j++)
#pragma unroll
            for (int r = 0; r < 4; r++) acc[mi][j][r] = 0.0f;

    const int nchunks = K >> 6;

    issue(0, 0); CP_COMMIT();
    issue(1, 1); CP_COMMIT();

    for (int c = 0; c < nchunks; c++) {
        CP_WAIT1();
        __syncthreads();

        const int st = c % 3;
        const uint32_t baseA = sbase + (uint32_t)st * STAGE_B;
        const uint32_t baseB = baseA + A_BYTES;

#pragma unroll
        for (int ks = 0; ks < 4; ks++) {
            uint32_t a[4][4], b[4][4];
            const uint32_t ka = (uint32_t)(32 * ks) + aK;
            const uint32_t kb = (uint32_t)(32 * ks) + bK;
#pragma unroll
            for (int mi = 0; mi < 4; mi++)
                LDSM4(a[mi], baseA + (aRow + mi * 16) * ROW_B + ka);
#pragma unroll
            for (int ni = 0; ni < 4; ni++)
                LDSM4(b[ni], baseB + (bRow + ni * 16) * ROW_B + kb);
#pragma unroll
            for (int mi = 0; mi < 4; mi++)
#pragma unroll
                for (int j = 0; j < 8; j++)
                    mma16816(acc[mi][j], a[mi], &b[j >> 1][(j & 1) * 2]);
        }

        if (c + 2 < nchunks) issue(c + 2, (c + 2) % 3);
        CP_COMMIT();
    }

    // ---- epilogue ----
#pragma unroll
    for (int mi = 0; mi < 4; mi++) {
        const int row0 = by * 256 + warp_m * 64 + mi * 16 + g;
#pragma unroll
        for (int j = 0; j < 8; j++) {
            const int col = bx * 128 + warp_n * 64 + j * 8 + 2 * tig;
            float2 v0, v1;
            v0.x = acc[mi][j][0] * alpha; v0.y = acc[mi][j][1] * alpha;
            v1.x = acc[mi][j][2] * alpha; v1.y = acc[mi][j][3] * alpha;
            if (MODE == 0 || MODE == 3) {
                const float b0 = bias[col], b1 = bias[col + 1];
                v0.x += b0; v0.y += b1;
                v1.x += b0; v1.y += b1;
            }
            if (MODE == 3) {
                const float2 r0 = *(const float2*)&resid0[(size_t)row0 * ldc + col];
                const float2 r1 = *(const float2*)&resid0[(size_t)(row0 + 8) * ldc + col];
                v0.x += r0.x; v0.y += r0.y;
                v1.x += r1.x; v1.y += r1.y;
            }
            if (MODE == 0 || MODE == 2) {
                *(__half2*)&Ch[(size_t)row0 * ldc + col] = __floats2half2_rn(v0.x, v0.y);
                *(__half2*)&Ch[(size_t)(row0 + 8) * ldc + col] = __floats2half2_rn(v1.x, v1.y);
            } else {
                *(float2*)&Cf[(size_t)row0 * ldc + col] = v0;
                *(float2*)&Cf[(size_t)(row0 + 8) * ldc + col] = v1;
            }
        }
    }
}

// ---------------------------------------------------------------------------
// fp32 -> fp16 elementwise (float4 granularity)
// ---------------------------------------------------------------------------
__global__ __launch_bounds__(256)
void cvt_half(const float* __restrict__ in, __half* __restrict__ out)
{
    const size_t i = (size_t)blockIdx.x * 256 + threadIdx.x;
    const float4 v = ((const float4*)in)[i];
    ((__half2*)out)[2 * i]     = __floats2half2_rn(v.x, v.y);
    ((__half2*)out)[2 * i + 1] = __floats2half2_rn(v.z, v.w);
}

// ---------------------------------------------------------------------------
// fp32 [z][R][C] -> fp16 transposed [z][C][R]
// ---------------------------------------------------------------------------
__global__ __launch_bounds__(256)
void cvtT(const float* __restrict__ in, __half* __restrict__ out, int R, int C)
{
    __shared__ float t[32][33];
    in  += (size_t)blockIdx.z * R * C;
    out += (size_t)blockIdx.z * R * C;
    const int c0 = blockIdx.x * 32, r0 = blockIdx.y * 32;
    const int tx = threadIdx.x & 31, ty = threadIdx.x >> 5;
#pragma unroll
    for (int i = 0; i < 32; i += 8)
        t[ty + i][tx] = in[(size_t)(r0 + ty + i) * C + c0 + tx];
    __syncthreads();
#pragma unroll
    for (int i = 0; i < 32; i += 8)
        out[(size_t)(c0 + ty + i) * R + r0 + tx] = __float2half(t[tx][ty + i]);
}

// ---------------------------------------------------------------------------
// fp16 [z][R][C] -> fp16 transposed [z][C][R]
// ---------------------------------------------------------------------------
__global__ __launch_bounds__(256)
void transpose16(const __half* __restrict__ in, __half* __restrict__ out, int R, int C)
{
    __shared__ __half t[32][34];
    in  += (size_t)blockIdx.z * R * C;
    out += (size_t)blockIdx.z * R * C;
    const int c0 = blockIdx.x * 32, r0 = blockIdx.y * 32;
    const int tx = threadIdx.x & 31, ty = threadIdx.x >> 5;
#pragma unroll
    for (int i = 0; i < 32; i += 8)
        t[ty + i][tx] = in[(size_t)(r0 + ty + i) * C + c0 + tx];
    __syncthreads();
#pragma unroll
    for (int i = 0; i < 32; i += 8)
        out[(size_t)(c0 + ty + i) * R + r0 + tx] = t[tx][ty + i];
}

// ---------------------------------------------------------------------------
// Row softmax fp32 in -> fp16 out
// ---------------------------------------------------------------------------
__global__ __launch_bounds__(256)
void softmax_kernel(const float* __restrict__ S, __half* __restrict__ P)
{
    __shared__ float red[256];
    const float* p = S + (size_t)blockIdx.x * Ss;
    __half* q = P + (size_t)blockIdx.x * Ss;
    const int t = threadIdx.x;

    float4 v0 = ((const float4*)p)[t];
    float4 v1 = ((const float4*)p)[t + 256];

    float m = fmaxf(fmaxf(fmaxf(v0.x, v0.y), fmaxf(v0.z, v0.w)),
                    fmaxf(fmaxf(v1.x, v1.y), fmaxf(v1.z, v1.w)));
    red[t] = m;
    __syncthreads();
    for (int s = 128; s > 0; s >>= 1) {
        if (t < s) red[t] = fmaxf(red[t], red[t + s]);
        __syncthreads();
    }
    m = red[0];
    __syncthreads();

    v0.x = expf(v0.x - m); v0.y = expf(v0.y - m);
    v0.z = expf(v0.z - m); v0.w = expf(v0.w - m);
    v1.x = expf(v1.x - m); v1.y = expf(v1.y - m);
    v1.z = expf(v1.z - m); v1.w = expf(v1.w - m);

    red[t] = v0.x + v0.y + v0.z + v0.w + v1.x + v1.y + v1.z + v1.w;
    __syncthreads();
    for (int s = 128; s > 0; s >>= 1) {
        if (t < s) red[t] += red[t + s];
        __syncthreads();
    }
    const float inv = 1.0f / red[0];

    ((__half2*)q)[2 * t]           = __floats2half2_rn(v0.x * inv, v0.y * inv);
    ((__half2*)q)[2 * t + 1]       = __floats2half2_rn(v0.z * inv, v0.w * inv);
    ((__half2*)q)[512 + 2 * t]     = __floats2half2_rn(v1.x * inv, v1.y * inv);
    ((__half2*)q)[512 + 2 * t + 1] = __floats2half2_rn(v1.z * inv, v1.w * inv);
}

// ---------------------------------------------------------------------------
extern "C" void kernel_launch(void* const* d_in, const int* in_sizes, int n_in,
                              void* d_out, int out_size)
{
    const float* x  = (const float*)d_in[0];
    const float* Wq = (const float*)d_in[1];
    const float* Wk = (const float*)d_in[2];
    const float* Wv = (const float*)d_in[3];
    const float* bq = (const float*)d_in[4];
    const float* bk = (const float*)d_in[5];
    const float* bv = (const float*)d_in[6];
    const float* Wo = (const float*)d_in[7];
    const float* bo = (const float*)d_in[8];
    float* out = (float*)d_out;

    __half *px16, *pWqt, *pWkt, *pWvt, *pWot, *pQ, *pK, *pV, *pVt, *pP, *pC;
    float *pS;
    cudaGetSymbolAddress((void**)&px16, gx16);
    cudaGetSymbolAddress((void**)&pWqt, gWqt16);
    cudaGetSymbolAddress((void**)&pWkt, gWkt16);
    cudaGetSymbolAddress((void**)&pWvt, gWvt16);
    cudaGetSymbolAddress((void**)&pWot, gWot16);
    cudaGetSymbolAddress((void**)&pQ, gQ16);
    cudaGetSymbolAddress((void**)&pK, gK16);
    cudaGetSymbolAddress((void**)&pV, gV16);
    cudaGetSymbolAddress((void**)&pVt, gVt16);
    cudaGetSymbolAddress((void**)&pS, gS);
    cudaGetSymbolAddress((void**)&pP, gP16);
    cudaGetSymbolAddress((void**)&pC, gC16);

    cudaFuncSetAttribute((const void*)hgemm<0>, cudaFuncAttributeMaxDynamicSharedMemorySize, HG_SMEM);
    cudaFuncSetAttribute((const void*)hgemm<1>, cudaFuncAttributeMaxDynamicSharedMemorySize, HG_SMEM);
    cudaFuncSetAttribute((const void*)hgemm<2>, cudaFuncAttributeMaxDynamicSharedMemorySize, HG_SMEM);
    cudaFuncSetAttribute((const void*)hgemm<3>, cudaFuncAttributeMaxDynamicSharedMemorySize, HG_SMEM);

    const float scale = 0.044194173824159216f;  // 1/sqrt(512)
    const dim3 blk(256);

    // 0) convert inputs to fp16 K-major operands
    cvt_half<<<Mrows * Dd / 1024, blk>>>(x, px16);
    cvtT<<<dim3(16, 16, Hh), blk>>>(Wq, pWqt, Dd, Dd);
    cvtT<<<dim3(16, 16, Hh), blk>>>(Wk, pWkt, Dd, Dd);
    cvtT<<<dim3(16, 16, Hh), blk>>>(Wv, pWvt, Dd, Dd);
    cvtT<<<dim3(16, 128, 1), blk>>>(Wo, pWot, CONCAT_K, Dd);

    // 1) merged QKV projections: [4096,512] = x16 @ W^T(h) per (which, h)
    hgemm<0><<<dim3(4, 16, 24), blk, HG_SMEM>>>(px16, pWqt, pWkt, pWvt,
                                                pQ, pK, pV, bq, bk, bv, nullptr,
                                                Dd, Dd, Dd, Dd, 1.0f);

    // 1b) V -> transposed [h][e][m]
    transpose16<<<dim3(16, 128, Hh), blk>>>(pV, pVt, Mrows, Dd);

    // 2) scores = scale * Q @ K^T, fp32 out
    hgemm<1><<<dim3(16, 8, Bb * Hh), blk, HG_SMEM>>>(pQ, pK, nullptr, nullptr,
                                                     pS, nullptr, nullptr,
                                                     nullptr, nullptr, nullptr, nullptr,
                                                     Dd, Dd, Dd, Ss, scale);

    // 3) softmax -> fp16 P
    softmax_kernel<<<Bb * Hh * Ss, 256>>>(pS, pP);

    // 4) O = P @ V -> fp16 concat layout [m][h*512+e]
    hgemm<2><<<dim3(4, 8, Bb * Hh), blk, HG_SMEM>>>(pP, pVt, nullptr, nullptr,
                                                    pC, nullptr, nullptr,
                                                    nullptr, nullptr, nullptr, nullptr,
                                                    Ss, Ss, Mrows, CONCAT_K, 1.0f);

    // 5) out = concat @ Wo^T + bo + x, fp32
    hgemm<3><<<dim3(4, 16, 1), blk, HG_SMEM>>>(pC, pWot, nullptr, nullptr,
                                               out, nullptr, nullptr,
                                               bo, nullptr, nullptr, x,
                                               CONCAT_K, CONCAT_K, CONCAT_K, Dd, 1.0f);
}

// round 8
// speedup vs baseline: 1.0364x; 1.0364x over previous
#include <cuda_runtime.h>
#include <cuda_fp16.h>
#include <math.h>
#include <stdint.h>

// Problem constants
#define Bb 2
#define Hh 8
#define Ss 2048
#define Dd 512
#define Mrows (Bb * Ss)          // 4096
#define CONCAT_K (Hh * Dd)       // 4096

// ---------------------------------------------------------------------------
// Scratch (device globals; allocation is forbidden)
// ---------------------------------------------------------------------------
__device__ __half gx16[(size_t)Mrows * Dd];                 // 4 MB   [m][d]
__device__ __half gWqt16[(size_t)Hh * Dd * Dd];             // 4 MB   [h][e][d]
__device__ __half gWkt16[(size_t)Hh * Dd * Dd];
__device__ __half gWvt16[(size_t)Hh * Dd * Dd];
__device__ __half gWot16[(size_t)Dd * CONCAT_K];            // 4 MB   [e][hd]
__device__ __half gQ16[(size_t)Hh * Mrows * Dd];            // 32 MB  [h][m][e]
__device__ __half gK16[(size_t)Hh * Mrows * Dd];            // 32 MB
__device__ __half gV16[(size_t)Hh * Mrows * Dd];            // 32 MB  [h][m][e]
__device__ __half gVt16[(size_t)Hh * Dd * Mrows];           // 32 MB  [h][e][m]
__device__ __half gS16[(size_t)Bb * Hh * Ss * Ss];          // 128 MB [z][q][k]  scores -> (in-place) softmax P
__device__ __half gC16[(size_t)Mrows * CONCAT_K];           // 32 MB  [m][h*D+e]

// ---------------------------------------------------------------------------
// helpers
// ---------------------------------------------------------------------------
__device__ __forceinline__ uint32_t smem_u32(const void* p) {
    uint32_t a;
    asm("{ .reg .u64 t; cvta.to.shared.u64 t, %1; cvt.u32.u64 %0, t; }" : "=r"(a) : "l"(p));
    return a;
}
#define CP16(dst, src) asm volatile("cp.async.cg.shared.global [%0], [%1], 16;" :: "r"(dst), "l"(src))
#define CP_COMMIT()    asm volatile("cp.async.commit_group;" ::: "memory")
#define CP_WAIT1()     asm volatile("cp.async.wait_group 1;" ::: "memory")

__device__ __forceinline__ uint32_t lds32(uint32_t a) {
    uint32_t v;
    asm volatile("ld.shared.b32 %0, [%1];" : "=r"(v) : "r"(a));
    return v;
}

__device__ __forceinline__ void mma16816(float* c, const uint32_t* a, const uint32_t* b) {
    asm volatile(
        "mma.sync.aligned.m16n8k16.row.col.f32.f16.f16.f32 "
        "{%0,%1,%2,%3},{%4,%5,%6,%7},{%8,%9},{%0,%1,%2,%3};\n"
        : "+f"(c[0]), "+f"(c[1]), "+f"(c[2]), "+f"(c[3])
        : "r"(a[0]), "r"(a[1]), "r"(a[2]), "r"(a[3]), "r"(b[0]), "r"(b[1]));
}

// ---------------------------------------------------------------------------
// fp16 GEMM: C = alpha * A @ B^T (+ bias) (+ resid)
// A: [M,K] fp16 K-major (lda halves), B: [N,K] fp16 K-major (ldb halves).
// CTA tile 128x128, K-chunk 32, 3-stage cp.async pipeline, 256 threads,
// 8 warps (2x4), warp tile 64x32, mma m16n8k16.  (identical core to the
// proven 827us kernel)
//
// MODE: 0 = merged QKV proj (z = which*8+h, half out),
//       1 = QK^T (z=b*8+h, HALF out, alpha),
//       2 = P@V (z=b*8+h, half out into concat),
//       3 = out proj (f32 + bias + resid)
// ---------------------------------------------------------------------------
#define ROW_B 80u
#define A_ST_BYTES (128u * ROW_B)        // 10240
#define STAGE_BYTES (2u * A_ST_BYTES)    // 20480
#define HG_SMEM (3 * 20480)              // 61440

template <int MODE>
__global__ __launch_bounds__(256)
void hgemm(const __half* __restrict__ A0, const __half* __restrict__ B0,
           const __half* __restrict__ B1v, const __half* __restrict__ B2v,
           void* __restrict__ C0, void* __restrict__ C1v, void* __restrict__ C2v,
           const float* __restrict__ bias0, const float* __restrict__ bias1,
           const float* __restrict__ bias2, const float* __restrict__ resid0,
           int K, int lda, int ldb, int ldc, float alpha)
{
    extern __shared__ char sm[];
    const uint32_t sbase = smem_u32(sm);

    const int tid = threadIdx.x;
    const int lane = tid & 31;
    const int wid = tid >> 5;
    const int g = lane >> 2;
    const int tig = lane & 3;
    const int warp_m = wid >> 2;   // 0..1
    const int warp_n = wid & 3;    // 0..3
    const int bx = blockIdx.x, by = blockIdx.y;

    const __half* A = A0;
    const __half* B = B0;
    const float* bias = bias0;
    float* Cf = (float*)C0;
    __half* Ch = (__half*)C0;
    {
        const int z = blockIdx.z;
        if (MODE == 0) {
            const int which = z >> 3, h = z & 7;
            const __half* W = (which == 0) ? B0 : ((which == 1) ? B1v : B2v);
            B = W + (size_t)h * Dd * Dd;
            __half* Co = (__half*)((which == 0) ? C0 : ((which == 1) ? C1v : C2v));
            Ch = Co + (size_t)h * Mrows * Dd;
            const float* bs = (which == 0) ? bias0 : ((which == 1) ? bias1 : bias2);
            bias = bs + (size_t)h * Dd;
        } else if (MODE == 1) {
            const int h = z & 7, b = z >> 3;
            const size_t off = ((size_t)h * Mrows + (size_t)b * Ss) * Dd;
            A += off; B += off;
            Ch += (size_t)z * Ss * Ss;
        } else if (MODE == 2) {
            const int h = z & 7, b = z >> 3;
            A += (size_t)z * Ss * Ss;
            B += (size_t)h * Dd * Mrows + (size_t)b * Ss;
            Ch += (size_t)b * Ss * CONCAT_K + (size_t)h * Dd;
        }
    }

    const __half* Arow = A + (size_t)(by * 128) * lda;
    const __half* Brow = B + (size_t)(bx * 128) * ldb;

    const int r0l = tid >> 2, r1l = (tid + 256) >> 2;
    const int f0l = tid & 3,  f1l = (tid + 256) & 3;

    auto issue = [&](int c, int st) {
        const __half* Ac = Arow + c * 32;
        const __half* Bc = Brow + c * 32;
        const uint32_t sA = sbase + (uint32_t)st * STAGE_BYTES;
        const uint32_t sB = sA + A_ST_BYTES;
        CP16(sA + (uint32_t)r0l * ROW_B + f0l * 16, Ac + (size_t)r0l * lda + f0l * 8);
        CP16(sB + (uint32_t)r0l * ROW_B + f0l * 16, Bc + (size_t)r0l * ldb + f0l * 8);
        CP16(sA + (uint32_t)r1l * ROW_B + f1l * 16, Ac + (size_t)r1l * lda + f1l * 8);
        CP16(sB + (uint32_t)r1l * ROW_B + f1l * 16, Bc + (size_t)r1l * ldb + f1l * 8);
    };

    float acc[4][4][4];
#pragma unroll
    for (int mi = 0; mi < 4; mi++)
#pragma unroll
        for (int ni = 0; ni < 4; ni++)
#pragma unroll
            for (int r = 0; r < 4; r++) acc[mi][ni][r] = 0.0f;

    const int nchunks = K >> 5;

    issue(0, 0); CP_COMMIT();
    issue(1, 1); CP_COMMIT();

    for (int c = 0; c < nchunks; c++) {
        CP_WAIT1();
        __syncthreads();

        const int st = c % 3;
        const uint32_t baseA = sbase + (uint32_t)st * STAGE_BYTES;
        const uint32_t baseB = baseA + A_ST_BYTES;
#pragma unroll
        for (int ks = 0; ks < 2; ks++) {
            const uint32_t kb = (uint32_t)(ks * 8 + tig) * 4;
            uint32_t a[4][4], b[4][2];
#pragma unroll
            for (int mi = 0; mi < 4; mi++) {
                const uint32_t ra = baseA + (uint32_t)(warp_m * 64 + mi * 16 + g) * ROW_B + kb;
                a[mi][0] = lds32(ra);
                a[mi][1] = lds32(ra + 8 * ROW_B);
                a[mi][2] = lds32(ra + 16);
                a[mi][3] = lds32(ra + 8 * ROW_B + 16);
            }
#pragma unroll
            for (int ni = 0; ni < 4; ni++) {
                const uint32_t rb = baseB + (uint32_t)(warp_n * 32 + ni * 8 + g) * ROW_B + kb;
                b[ni][0] = lds32(rb);
                b[ni][1] = lds32(rb + 16);
            }
#pragma unroll
            for (int mi = 0; mi < 4; mi++)
#pragma unroll
                for (int ni = 0; ni < 4; ni++)
                    mma16816(acc[mi][ni], a[mi], b[ni]);
        }

        if (c + 2 < nchunks) issue(c + 2, (c + 2) % 3);
        CP_COMMIT();
    }

    // epilogue
#pragma unroll
    for (int mi = 0; mi < 4; mi++) {
        const int row0 = by * 128 + warp_m * 64 + mi * 16 + g;
#pragma unroll
        for (int ni = 0; ni < 4; ni++) {
            const int col = bx * 128 + warp_n * 32 + ni * 8 + 2 * tig;
            float2 v0, v1;
            v0.x = acc[mi][ni][0] * alpha; v0.y = acc[mi][ni][1] * alpha;
            v1.x = acc[mi][ni][2] * alpha; v1.y = acc[mi][ni][3] * alpha;
            if (MODE == 0 || MODE == 3) {
                const float b0 = bias[col], b1 = bias[col + 1];
                v0.x += b0; v0.y += b1;
                v1.x += b0; v1.y += b1;
            }
            if (MODE == 3) {
                const float2 r0 = *(const float2*)&resid0[(size_t)row0 * ldc + col];
                const float2 r1 = *(const float2*)&resid0[(size_t)(row0 + 8) * ldc + col];
                v0.x += r0.x; v0.y += r0.y;
                v1.x += r1.x; v1.y += r1.y;
            }
            if (MODE == 3) {
                *(float2*)&Cf[(size_t)row0 * ldc + col] = v0;
                *(float2*)&Cf[(size_t)(row0 + 8) * ldc + col] = v1;
            } else {
                *(__half2*)&Ch[(size_t)row0 * ldc + col] = __floats2half2_rn(v0.x, v0.y);
                *(__half2*)&Ch[(size_t)(row0 + 8) * ldc + col] = __floats2half2_rn(v1.x, v1.y);
            }
        }
    }
}

// ---------------------------------------------------------------------------
// fp32 -> fp16 elementwise (float4 granularity)
// ---------------------------------------------------------------------------
__global__ __launch_bounds__(256)
void cvt_half(const float* __restrict__ in, __half* __restrict__ out)
{
    const size_t i = (size_t)blockIdx.x * 256 + threadIdx.x;
    const float4 v = ((const float4*)in)[i];
    ((__half2*)out)[2 * i]     = __floats2half2_rn(v.x, v.y);
    ((__half2*)out)[2 * i + 1] = __floats2half2_rn(v.z, v.w);
}

// ---------------------------------------------------------------------------
// merged fp32 [z][512][512] -> fp16 transposed, 3 weight tensors (z = which*8+h)
// ---------------------------------------------------------------------------
__global__ __launch_bounds__(256)
void cvtT3(const float* __restrict__ q, const float* __restrict__ k,
           const float* __restrict__ v,
           __half* __restrict__ qo, __half* __restrict__ ko, __half* __restrict__ vo)
{
    __shared__ float t[32][33];
    const int which = blockIdx.z >> 3, h = blockIdx.z & 7;
    const float* in = ((which == 0) ? q : (which == 1) ? k : v) + (size_t)h * Dd * Dd;
    __half* out = ((which == 0) ? qo : (which == 1) ? ko : vo) + (size_t)h * Dd * Dd;
    const int c0 = blockIdx.x * 32, r0 = blockIdx.y * 32;
    const int tx = threadIdx.x & 31, ty = threadIdx.x >> 5;
#pragma unroll
    for (int i = 0; i < 32; i += 8)
        t[ty + i][tx] = in[(size_t)(r0 + ty + i) * Dd + c0 + tx];
    __syncthreads();
#pragma unroll
    for (int i = 0; i < 32; i += 8)
        out[(size_t)(c0 + ty + i) * Dd + r0 + tx] = __float2half(t[tx][ty + i]);
}

// ---------------------------------------------------------------------------
// fp32 [z][R][C] -> fp16 transposed [z][C][R]
// ---------------------------------------------------------------------------
__global__ __launch_bounds__(256)
void cvtT(const float* __restrict__ in, __half* __restrict__ out, int R, int C)
{
    __shared__ float t[32][33];
    in  += (size_t)blockIdx.z * R * C;
    out += (size_t)blockIdx.z * R * C;
    const int c0 = blockIdx.x * 32, r0 = blockIdx.y * 32;
    const int tx = threadIdx.x & 31, ty = threadIdx.x >> 5;
#pragma unroll
    for (int i = 0; i < 32; i += 8)
        t[ty + i][tx] = in[(size_t)(r0 + ty + i) * C + c0 + tx];
    __syncthreads();
#pragma unroll
    for (int i = 0; i < 32; i += 8)
        out[(size_t)(c0 + ty + i) * R + r0 + tx] = __float2half(t[tx][ty + i]);
}

// ---------------------------------------------------------------------------
// fp16 [z][R][C] -> fp16 transposed [z][C][R]
// ---------------------------------------------------------------------------
__global__ __launch_bounds__(256)
void transpose16(const __half* __restrict__ in, __half* __restrict__ out, int R, int C)
{
    __shared__ __half t[32][34];
    in  += (size_t)blockIdx.z * R * C;
    out += (size_t)blockIdx.z * R * C;
    const int c0 = blockIdx.x * 32, r0 = blockIdx.y * 32;
    const int tx = threadIdx.x & 31, ty = threadIdx.x >> 5;
#pragma unroll
    for (int i = 0; i < 32; i += 8)
        t[ty + i][tx] = in[(size_t)(r0 + ty + i) * C + c0 + tx];
    __syncthreads();
#pragma unroll
    for (int i = 0; i < 32; i += 8)
        out[(size_t)(c0 + ty + i) * R + r0 + tx] = t[tx][ty + i];
}

// ---------------------------------------------------------------------------
// Row softmax, fp16 in -> fp16 out, IN PLACE.
// One block per row of 2048; 256 threads x 8 halves (one uint4 each).
// ---------------------------------------------------------------------------
__global__ __launch_bounds__(256)
void softmax16_kernel(__half* __restrict__ S)
{
    __shared__ float red[256];
    __half* p = S + (size_t)blockIdx.x * Ss;
    const int t = threadIdx.x;

    uint4 raw = ((const uint4*)p)[t];
    const __half2* hp = (const __half2*)&raw;
    float2 f[4];
#pragma unroll
    for (int i = 0; i < 4; i++) f[i] = __half22float2(hp[i]);

    float m = f[0].x;
#pragma unroll
    for (int i = 0; i < 4; i++) m = fmaxf(m, fmaxf(f[i].x, f[i].y));
    red[t] = m;
    __syncthreads();
    for (int s = 128; s > 0; s >>= 1) {
        if (t < s) red[t] = fmaxf(red[t], red[t + s]);
        __syncthreads();
    }
    m = red[0];
    __syncthreads();

    float sum = 0.0f;
#pragma unroll
    for (int i = 0; i < 4; i++) {
        f[i].x = expf(f[i].x - m); f[i].y = expf(f[i].y - m);
        sum += f[i].x + f[i].y;
    }
    red[t] = sum;
    __syncthreads();
    for (int s = 128; s > 0; s >>= 1) {
        if (t < s) red[t] += red[t + s];
        __syncthreads();
    }
    const float inv = 1.0f / red[0];

    uint4 outw;
    __half2* op = (__half2*)&outw;
#pragma unroll
    for (int i = 0; i < 4; i++)
        op[i] = __floats2half2_rn(f[i].x * inv, f[i].y * inv);
    ((uint4*)p)[t] = outw;
}

// ---------------------------------------------------------------------------
extern "C" void kernel_launch(void* const* d_in, const int* in_sizes, int n_in,
                              void* d_out, int out_size)
{
    const float* x  = (const float*)d_in[0];
    const float* Wq = (const float*)d_in[1];
    const float* Wk = (const float*)d_in[2];
    const float* Wv = (const float*)d_in[3];
    const float* bq = (const float*)d_in[4];
    const float* bk = (const float*)d_in[5];
    const float* bv = (const float*)d_in[6];
    const float* Wo = (const float*)d_in[7];
    const float* bo = (const float*)d_in[8];
    float* out = (float*)d_out;

    __half *px16, *pWqt, *pWkt, *pWvt, *pWot, *pQ, *pK, *pV, *pVt, *pS, *pC;
    cudaGetSymbolAddress((void**)&px16, gx16);
    cudaGetSymbolAddress((void**)&pWqt, gWqt16);
    cudaGetSymbolAddress((void**)&pWkt, gWkt16);
    cudaGetSymbolAddress((void**)&pWvt, gWvt16);
    cudaGetSymbolAddress((void**)&pWot, gWot16);
    cudaGetSymbolAddress((void**)&pQ, gQ16);
    cudaGetSymbolAddress((void**)&pK, gK16);
    cudaGetSymbolAddress((void**)&pV, gV16);
    cudaGetSymbolAddress((void**)&pVt, gVt16);
    cudaGetSymbolAddress((void**)&pS, gS16);
    cudaGetSymbolAddress((void**)&pC, gC16);

    cudaFuncSetAttribute((const void*)hgemm<0>, cudaFuncAttributeMaxDynamicSharedMemorySize, HG_SMEM);
    cudaFuncSetAttribute((const void*)hgemm<1>, cudaFuncAttributeMaxDynamicSharedMemorySize, HG_SMEM);
    cudaFuncSetAttribute((const void*)hgemm<2>, cudaFuncAttributeMaxDynamicSharedMemorySize, HG_SMEM);
    cudaFuncSetAttribute((const void*)hgemm<3>, cudaFuncAttributeMaxDynamicSharedMemorySize, HG_SMEM);

    const float scale = 0.044194173824159216f;  // 1/sqrt(512)
    const dim3 blk(256);

    // 0) convert inputs to fp16 K-major operands
    cvt_half<<<Mrows * Dd / 1024, blk>>>(x, px16);
    cvtT3<<<dim3(16, 16, 24), blk>>>(Wq, Wk, Wv, pWqt, pWkt, pWvt);
    cvtT<<<dim3(16, 128, 1), blk>>>(Wo, pWot, CONCAT_K, Dd);

    // 1) merged QKV projections: [4096,512] = x16 @ W^T(h) per (which, h)
    hgemm<0><<<dim3(4, 32, 24), blk, HG_SMEM>>>(px16, pWqt, pWkt, pWvt,
                                                pQ, pK, pV, bq, bk, bv, nullptr,
                                                Dd, Dd, Dd, Dd, 1.0f);

    // 1b) V -> transposed [h][e][m]
    transpose16<<<dim3(16, 128, Hh), blk>>>(pV, pVt, Mrows, Dd);

    // 2) scores = scale * Q @ K^T, fp16 out
    hgemm<1><<<dim3(16, 16, Bb * Hh), blk, HG_SMEM>>>(pQ, pK, nullptr, nullptr,
                                                      pS, nullptr, nullptr,
                                                      nullptr, nullptr, nullptr, nullptr,
                                                      Dd, Dd, Dd, Ss, scale);

    // 3) softmax in place (fp16)
    softmax16_kernel<<<Bb * Hh * Ss, 256>>>(pS);

    // 4) O = P @ V -> fp16 concat layout [m][h*512+e]
    hgemm<2><<<dim3(4, 16, Bb * Hh), blk, HG_SMEM>>>(pS, pVt, nullptr, nullptr,
                                                     pC, nullptr, nullptr,
                                                     nullptr, nullptr, nullptr, nullptr,
                                                     Ss, Ss, Mrows, CONCAT_K, 1.0f);

    // 5) out = concat @ Wo^T + bo + x, fp32
    hgemm<3><<<dim3(4, 32, 1), blk, HG_SMEM>>>(pC, pWot, nullptr, nullptr,
                                               out, nullptr, nullptr,
                                               bo, nullptr, nullptr, x,
                                               CONCAT_K, CONCAT_K, CONCAT_K, Dd, 1.0f);
}